// round 14
// baseline (speedup 1.0000x reference)
#include <cuda_runtime.h>
#include <cuda_bf16.h>
#include <cstdint>
#include <math.h>

// CharDecoder: 8192 LSTM decode sequences, H=512, A=128, C=20 steps.
// NUMERICS CONTRACT (frozen, verified rel_err=2.4854e-7):
//  - per-output single fp32 accumulator, strictly ascending-k chain, acc=0,
//    bias last; gates = (xw + hw) + bias; XLA tanh/sigmoid.
// R14: packed fma.rn.f32x2 for the gate GEMM (2 fp32 FMAs / fma slot).
//  - weights staged interleaved: Ws[(P*128+j)*36 + 2*kk + half] -> LDS.128 = packed pairs
//  - h stored duplicated [r][k][2] -> LDS.128 = dup pairs; single h buffer,
//    new h kept in registers across the 4 gate chunks, written after a barrier.
// Each f32x2 lane is IEEE fp32 RN -> chains bit-identical to scalar version.

#define Hdim   512
#define Qdim   256
#define Adim   128
#define Csteps 20
#define Rrows  28
#define NTHR   512
#define KT     16
#define WSTR   20          // scalar Ws stride (h0/logits paths)
#define WP_STR 36          // paired Ws stride: 16k*2 + 4 pad (4j mod 32 distinct/phase)
#define NROWS  8192
#define NCTAS  293

__device__ float g_wihT[Adim * 4 * Hdim];

__global__ void transpose_wih_kernel(const float* __restrict__ w_ih) {
    int id = blockIdx.x * 256 + threadIdx.x;
    if (id < Adim * 4 * Hdim) {
        int a = id >> 11;
        int n = id & 2047;
        g_wihT[id] = w_ih[n * Adim + a];
    }
}

__device__ __forceinline__ float tanh_xla(float x) {
    float ax = fabsf(x);
    if (ax < 4e-4f) return x;
    float xc = fminf(fmaxf(x, -7.90531110763549805f), 7.90531110763549805f);
    float x2 = __fmul_rn(xc, xc);
    float p = fmaf(x2, -2.76076847742355e-16f, 2.00018790482477e-13f);
    p = fmaf(x2, p, -8.60467152213735e-11f);
    p = fmaf(x2, p,  5.12229709037114e-08f);
    p = fmaf(x2, p,  1.48572235717979e-05f);
    p = fmaf(x2, p,  6.37261928875436e-04f);
    p = fmaf(x2, p,  4.89352455891786e-03f);
    p = __fmul_rn(xc, p);
    float q = fmaf(x2, 1.19825839466702e-06f, 1.18534705686654e-04f);
    q = fmaf(x2, q, 2.26843463243900e-03f);
    q = fmaf(x2, q, 4.89352518554385e-03f);
    return __fdiv_rn(p, q);
}

__device__ __forceinline__ float sigmoid_xla(float x) {
    float th = tanh_xla(__fmul_rn(0.5f, x));
    return __fadd_rn(__fmul_rn(0.5f, th), 0.5f);
}

// packed fp32x2 FMA: d.lo = fma.rn(a.lo,b.lo,d.lo), d.hi = fma.rn(a.hi,b.hi,d.hi)
__device__ __forceinline__ void ffma2(unsigned long long& acc,
                                      unsigned long long a,
                                      unsigned long long b) {
    asm("fma.rn.f32x2 %0, %1, %2, %0;" : "+l"(acc) : "l"(a), "l"(b));
}

// Scalar tiled GEMM (h0 path): acc[7][M], ascending-k chain. act non-dup.
template<int M, int KTOT>
__device__ __forceinline__ void gemm_scalar(
    float (&acc)[7][M],
    const float* __restrict__ gW, int gStride,
    const float* __restrict__ act, int actStride,
    float* __restrict__ Ws, int t, int ig, int j)
{
    const int COLS = M * 128;
    for (int k0 = 0; k0 < KTOT; k0 += KT) {
        __syncthreads();
        const int tasks = COLS * (KT / 4);
        for (int id = t; id < tasks; id += NTHR) {
            int c = id >> 2;
            int s = id & 3;
            float4 v = *(const float4*)(gW + (long)c * gStride + k0 + s * 4);
            *(float4*)(Ws + c * WSTR + s * 4) = v;
        }
        __syncthreads();
        #pragma unroll
        for (int kk = 0; kk < KT; kk += 4) {
            float4 av[7];
            #pragma unroll
            for (int rr = 0; rr < 7; rr++)
                av[rr] = *(const float4*)(act + (ig * 7 + rr) * actStride + k0 + kk);
            #pragma unroll
            for (int m = 0; m < M; m++) {
                float4 wv = *(const float4*)(Ws + (j + 128 * m) * WSTR + kk);
                #pragma unroll
                for (int rr = 0; rr < 7; rr++) {
                    acc[rr][m] = fmaf(av[rr].x, wv.x, acc[rr][m]);
                    acc[rr][m] = fmaf(av[rr].y, wv.y, acc[rr][m]);
                    acc[rr][m] = fmaf(av[rr].z, wv.z, acc[rr][m]);
                    acc[rr][m] = fmaf(av[rr].w, wv.w, acc[rr][m]);
                }
            }
        }
    }
}

__global__ __launch_bounds__(NTHR, 1)
void chardecoder_kernel(
    const float* __restrict__ qr,     // [8192,256]
    const float* __restrict__ w_in,   // [512,256]
    const float* __restrict__ b_in,   // [512]
    const float* __restrict__ w_hh,   // [2048,512]
    const float* __restrict__ b_ih,   // [2048]
    const float* __restrict__ b_hh,   // [2048]
    const float* __restrict__ w_out,  // [128,512]
    const float* __restrict__ b_out,  // [128]
    float* __restrict__ out)          // [8192,20,128]
{
    extern __shared__ float sm[];
    float* hS    = sm;                        // 28*512*2 dup  (28672)
    float* cS    = hS + Rrows * Hdim * 2;     // 28*512 (also qr temp 28*256)
    float* Ws    = cS + Rrows * Hdim;         // 10240 floats (scalar 512*20 max)
    float* biasS = Ws + 10240;                // 2048
    float* boutS = biasS + 4 * Hdim;          // 128
    int*   idxS  = (int*)(boutS + Adim);      // 32
    float* logitsS = Ws;                      // reuse after logits GEMM

    const int t = threadIdx.x;
    const int rowBase = blockIdx.x * Rrows;
    const int ig = t >> 7;       // 0..3, 7 rows each
    const int j  = t & 127;      // column lane
    const int warp = t >> 5, lane = t & 31;

    // ---- prologue ----
    for (int n = t; n < 4 * Hdim; n += NTHR) biasS[n] = __fadd_rn(b_ih[n], b_hh[n]);
    if (t < Adim) boutS[t] = b_out[t];
    for (int r = t; r < 32; r += NTHR) idxS[r] = 0;

    // stage qr into c region (temp, non-dup, stride 256)
    for (int x = t; x < Rrows * Qdim; x += NTHR) {
        int r = x >> 8;
        int k = x & 255;
        int rg = min(rowBase + r, NROWS - 1);
        cS[r * Qdim + k] = qr[(long)rg * Qdim + k];
    }
    __syncthreads();

    // ---- h0 = qr @ w_in.T + b_in (scalar path) ; then c = 0 ----
    {
        float acc[7][4];
        #pragma unroll
        for (int m = 0; m < 4; m++)
            #pragma unroll
            for (int rr = 0; rr < 7; rr++) acc[rr][m] = 0.0f;
        gemm_scalar<4, Qdim>(acc, w_in, Qdim, cS, Qdim, Ws, t, ig, j);
        __syncthreads();   // all qr reads done before c overwrite
        #pragma unroll
        for (int m = 0; m < 4; m++) {
            int n = j + 128 * m;
            float bv = b_in[n];
            #pragma unroll
            for (int rr = 0; rr < 7; rr++) {
                int r = ig * 7 + rr;
                float v = __fadd_rn(acc[rr][m], bv);
                *(float2*)(hS + (r * Hdim + n) * 2) = make_float2(v, v);
            }
        }
        for (int x = t; x < Rrows * Hdim; x += NTHR) cS[x] = 0.0f;
    }
    __syncthreads();

    for (int step = 0; step < Csteps; step++) {
        float hreg[4][7];

        // ---- gates: paired f32x2 GEMM over w_hh, per 128-col chunk jc ----
        for (int jc = 0; jc < 4; jc++) {
            unsigned long long accp[7][2];
            #pragma unroll
            for (int rr = 0; rr < 7; rr++) { accp[rr][0] = 0ULL; accp[rr][1] = 0ULL; }

            for (int k0 = 0; k0 < Hdim; k0 += KT) {
                __syncthreads();
                // stage interleaved pairs: Ws[(P*128+col)*36 + 2*kk + half]
                #pragma unroll
                for (int it = 0; it < 4; it++) {
                    int id = t + it * NTHR;
                    int c = id >> 2;          // 0..511
                    int s = id & 3;
                    int m = c >> 7;           // 0..3
                    int col = c & 127;
                    int n = m * Hdim + jc * 128 + col;
                    float4 v = *(const float4*)(w_hh + (long)n * Hdim + k0 + s * 4);
                    float* base = Ws + ((m >> 1) * 128 + col) * WP_STR + (m & 1);
                    base[(4 * s + 0) * 2] = v.x;
                    base[(4 * s + 1) * 2] = v.y;
                    base[(4 * s + 2) * 2] = v.z;
                    base[(4 * s + 3) * 2] = v.w;
                }
                __syncthreads();

                #pragma unroll
                for (int kp = 0; kp < KT / 2; kp++) {
                    int kg = k0 + 2 * kp;
                    ulonglong2 av[7];
                    #pragma unroll
                    for (int rr = 0; rr < 7; rr++)
                        av[rr] = *(const ulonglong2*)(hS + ((ig * 7 + rr) * Hdim + kg) * 2);
                    ulonglong2 wv0 = *(const ulonglong2*)(Ws + (0 * 128 + j) * WP_STR + 4 * kp);
                    ulonglong2 wv1 = *(const ulonglong2*)(Ws + (1 * 128 + j) * WP_STR + 4 * kp);
                    // k = kg  (ascending within each chain)
                    #pragma unroll
                    for (int rr = 0; rr < 7; rr++) {
                        ffma2(accp[rr][0], av[rr].x, wv0.x);
                        ffma2(accp[rr][1], av[rr].x, wv1.x);
                    }
                    // k = kg+1
                    #pragma unroll
                    for (int rr = 0; rr < 7; rr++) {
                        ffma2(accp[rr][0], av[rr].y, wv0.y);
                        ffma2(accp[rr][1], av[rr].y, wv1.y);
                    }
                }
            }

            // epilogue: unpack, (xw + hw) + bias, activations, c update
            #pragma unroll
            for (int rr = 0; rr < 7; rr++) {
                int r = ig * 7 + rr;
                int xidx = idxS[r];
                float g4[4];
                #pragma unroll
                for (int P = 0; P < 2; P++) {
                    unsigned int lo, hi;
                    asm("mov.b64 {%0,%1}, %2;" : "=r"(lo), "=r"(hi) : "l"(accp[rr][P]));
                    int n0 = (2 * P) * Hdim + jc * 128 + j;
                    int n1 = (2 * P + 1) * Hdim + jc * 128 + j;
                    g4[2 * P] = __fadd_rn(
                        __fadd_rn(g_wihT[xidx * (4 * Hdim) + n0], __uint_as_float(lo)),
                        biasS[n0]);
                    g4[2 * P + 1] = __fadd_rn(
                        __fadd_rn(g_wihT[xidx * (4 * Hdim) + n1], __uint_as_float(hi)),
                        biasS[n1]);
                }
                float ii = sigmoid_xla(g4[0]);
                float ff = sigmoid_xla(g4[1]);
                float gg = tanh_xla(g4[2]);
                float oo = sigmoid_xla(g4[3]);
                int jj = jc * 128 + j;
                float cold = cS[r * Hdim + jj];
                float cc = __fadd_rn(__fmul_rn(ff, cold), __fmul_rn(ii, gg));
                cS[r * Hdim + jj] = cc;
                hreg[jc][rr] = __fmul_rn(oo, tanh_xla(cc));
            }
        }

        // ---- publish new h (dup) after all gate GEMMs read old h ----
        __syncthreads();
        #pragma unroll
        for (int jc2 = 0; jc2 < 4; jc2++)
            #pragma unroll
            for (int rr = 0; rr < 7; rr++) {
                int r = ig * 7 + rr;
                int jj = jc2 * 128 + j;
                float v = hreg[jc2][rr];
                *(float2*)(hS + (r * Hdim + jj) * 2) = make_float2(v, v);
            }
        __syncthreads();

        // ---- logits = h @ w_out.T + b_out (scalar, dup-aware act reads) ----
        {
            float acc[7];
            #pragma unroll
            for (int rr = 0; rr < 7; rr++) acc[rr] = 0.0f;
            for (int k0 = 0; k0 < Hdim; k0 += KT) {
                __syncthreads();
                {   // stage 128 cols x KT: 512 tasks, 1 per thread
                    int c = t >> 2;
                    int s = t & 3;
                    float4 v = *(const float4*)(w_out + (long)c * Hdim + k0 + s * 4);
                    *(float4*)(Ws + c * WSTR + s * 4) = v;
                }
                __syncthreads();
                #pragma unroll
                for (int kk = 0; kk < KT; kk += 2) {
                    float2 wv = *(const float2*)(Ws + j * WSTR + kk);
                    #pragma unroll
                    for (int rr = 0; rr < 7; rr++) {
                        float4 av = *(const float4*)(hS + ((ig * 7 + rr) * Hdim + k0 + kk) * 2);
                        acc[rr] = fmaf(av.x, wv.x, acc[rr]);   // h[k] (dup lo)
                        acc[rr] = fmaf(av.z, wv.y, acc[rr]);   // h[k+1]
                    }
                }
            }
            __syncthreads();   // Ws free -> logits buffer
            #pragma unroll
            for (int rr = 0; rr < 7; rr++) {
                int r = ig * 7 + rr;
                int rg = min(rowBase + r, NROWS - 1);
                float v = __fadd_rn(acc[rr], boutS[j]);
                logitsS[r * Adim + j] = v;
                out[((long)rg * Csteps + step) * Adim + j] = v;
            }
        }
        __syncthreads();

        // ---- argmax per row (first-max semantics) ----
        for (int r = warp; r < Rrows; r += 16) {
            float best = -INFINITY; int bi = 0;
            #pragma unroll
            for (int q = 0; q < 4; q++) {
                int a = lane + 32 * q;
                float v = logitsS[r * Adim + a];
                if (v > best) { best = v; bi = a; }
            }
            #pragma unroll
            for (int off = 16; off; off >>= 1) {
                float ov = __shfl_down_sync(0xffffffff, best, off);
                int   oi = __shfl_down_sync(0xffffffff, bi, off);
                if (ov > best || (ov == best && oi < bi)) { best = ov; bi = oi; }
            }
            if (lane == 0) idxS[r] = bi;
        }
        __syncthreads();
    }
}

extern "C" void kernel_launch(void* const* d_in, const int* in_sizes, int n_in,
                              void* d_out, int out_size) {
    const float* qr    = (const float*)d_in[0];
    const float* w_in  = (const float*)d_in[1];
    const float* b_in  = (const float*)d_in[2];
    const float* w_ih  = (const float*)d_in[3];
    const float* w_hh  = (const float*)d_in[4];
    const float* b_ih  = (const float*)d_in[5];
    const float* b_hh  = (const float*)d_in[6];
    const float* w_out = (const float*)d_in[7];
    const float* b_out = (const float*)d_in[8];
    float* out = (float*)d_out;

    transpose_wih_kernel<<<(Adim * 4 * Hdim + 255) / 256, 256>>>(w_ih);

    const int smemFloats = Rrows * Hdim * 2   // h dup
                         + Rrows * Hdim       // c
                         + 10240              // Ws
                         + 4 * Hdim + Adim + 32;
    const int smemBytes = smemFloats * 4;
    cudaFuncSetAttribute(chardecoder_kernel,
                         cudaFuncAttributeMaxDynamicSharedMemorySize, smemBytes);
    chardecoder_kernel<<<NCTAS, NTHR, smemBytes>>>(
        qr, w_in, b_in, w_hh, b_ih, b_hh, w_out, b_out, out);
}

// round 16
// speedup vs baseline: 1.0548x; 1.0548x over previous
#include <cuda_runtime.h>
#include <cuda_bf16.h>
#include <cstdint>
#include <math.h>

// CharDecoder: 8192 LSTM decode sequences, H=512, A=128, C=20 steps.
// NUMERICS CONTRACT (frozen, verified rel_err=2.4854e-7):
//  - per-output single fp32 accumulator, strictly ascending-k chain, acc=0,
//    bias last; gates = (xw + hw) + bias; XLA tanh/sigmoid. FFMA2 lanes are
//    IEEE fp32 RN (validated bit-exact in R14).
// R15: FFMA2 with REGISTER pairing (no SMEM dup, scalar Ws layout/staging),
//      double-buffered weight staging (1 sync/tile), c in thread-local,
//      h ping-pong in SMEM. LDS count per 4-k identical to scalar R13.

#define Hdim   512
#define Qdim   256
#define Adim   128
#define Csteps 20
#define Rrows  28
#define NTHR   512
#define KT     16
#define WSTR   20
#define NROWS  8192
#define NCTAS  293

__device__ float g_wihT[Adim * 4 * Hdim];

__global__ void transpose_wih_kernel(const float* __restrict__ w_ih) {
    int id = blockIdx.x * 256 + threadIdx.x;
    if (id < Adim * 4 * Hdim) {
        int a = id >> 11;
        int n = id & 2047;
        g_wihT[id] = w_ih[n * Adim + a];
    }
}

__device__ __forceinline__ float tanh_xla(float x) {
    float ax = fabsf(x);
    if (ax < 4e-4f) return x;
    float xc = fminf(fmaxf(x, -7.90531110763549805f), 7.90531110763549805f);
    float x2 = __fmul_rn(xc, xc);
    float p = fmaf(x2, -2.76076847742355e-16f, 2.00018790482477e-13f);
    p = fmaf(x2, p, -8.60467152213735e-11f);
    p = fmaf(x2, p,  5.12229709037114e-08f);
    p = fmaf(x2, p,  1.48572235717979e-05f);
    p = fmaf(x2, p,  6.37261928875436e-04f);
    p = fmaf(x2, p,  4.89352455891786e-03f);
    p = __fmul_rn(xc, p);
    float q = fmaf(x2, 1.19825839466702e-06f, 1.18534705686654e-04f);
    q = fmaf(x2, q, 2.26843463243900e-03f);
    q = fmaf(x2, q, 4.89352518554385e-03f);
    return __fdiv_rn(p, q);
}

__device__ __forceinline__ float sigmoid_xla(float x) {
    float th = tanh_xla(__fmul_rn(0.5f, x));
    return __fadd_rn(__fmul_rn(0.5f, th), 0.5f);
}

__device__ __forceinline__ void ffma2(unsigned long long& d,
                                      unsigned long long a,
                                      unsigned long long b) {
    asm("fma.rn.f32x2 %0, %1, %2, %0;" : "+l"(d) : "l"(a), "l"(b));
}
__device__ __forceinline__ unsigned long long pack2(float lo, float hi) {
    unsigned long long r;
    asm("mov.b64 %0, {%1, %2};" : "=l"(r)
        : "r"(__float_as_uint(lo)), "r"(__float_as_uint(hi)));
    return r;
}

__global__ __launch_bounds__(NTHR, 1)
void chardecoder_kernel(
    const float* __restrict__ qr,
    const float* __restrict__ w_in,
    const float* __restrict__ b_in,
    const float* __restrict__ w_hh,
    const float* __restrict__ b_ih,
    const float* __restrict__ b_hh,
    const float* __restrict__ w_out,
    const float* __restrict__ b_out,
    float* __restrict__ out)
{
    extern __shared__ float sm[];
    float* hA    = sm;                        // 14336
    float* hB    = hA + Rrows * Hdim;         // 14336
    float* Wp    = hB + Rrows * Hdim;         // 20480 (two scalar Ws buffers)
    float* biasS = Wp + 2 * 10240;            // 2048
    float* boutS = biasS + 4 * Hdim;          // 128
    int*   idxS  = (int*)(boutS + Adim);      // 32
    float* logitsS = Wp;

    const int t = threadIdx.x;
    const int rowBase = blockIdx.x * Rrows;
    const int ig = t >> 7;
    const int j  = t & 127;
    const int warp = t >> 5, lane = t & 31;

    float cloc[28];          // thread-private cell state (local)
    #pragma unroll
    for (int i = 0; i < 28; i++) cloc[i] = 0.0f;

    for (int n = t; n < 4 * Hdim; n += NTHR) biasS[n] = __fadd_rn(b_ih[n], b_hh[n]);
    if (t < Adim) boutS[t] = b_out[t];
    for (int r = t; r < 32; r += NTHR) idxS[r] = 0;

    // qr into hB (stride Qdim)
    for (int x = t; x < Rrows * Qdim; x += NTHR) {
        int r = x >> 8;
        int k = x & 255;
        int rg = min(rowBase + r, NROWS - 1);
        hB[r * Qdim + k] = qr[(long)rg * Qdim + k];
    }
    __syncthreads();

    // ---- h0 = qr @ w_in.T + b_in (scalar, single-buffered) ----
    {
        float acc[7][4];
        #pragma unroll
        for (int m = 0; m < 4; m++)
            #pragma unroll
            for (int rr = 0; rr < 7; rr++) acc[rr][m] = 0.0f;
        for (int k0 = 0; k0 < Qdim; k0 += KT) {
            __syncthreads();
            #pragma unroll
            for (int it = 0; it < 4; it++) {
                int id = t + it * NTHR;
                int c = id >> 2, s = id & 3;
                float4 v = *(const float4*)(w_in + (long)c * Qdim + k0 + s * 4);
                *(float4*)(Wp + c * WSTR + s * 4) = v;
            }
            __syncthreads();
            #pragma unroll
            for (int kk = 0; kk < KT; kk += 4) {
                float4 av[7];
                #pragma unroll
                for (int rr = 0; rr < 7; rr++)
                    av[rr] = *(const float4*)(hB + (ig * 7 + rr) * Qdim + k0 + kk);
                #pragma unroll
                for (int m = 0; m < 4; m++) {
                    float4 wv = *(const float4*)(Wp + (j + 128 * m) * WSTR + kk);
                    #pragma unroll
                    for (int rr = 0; rr < 7; rr++) {
                        acc[rr][m] = fmaf(av[rr].x, wv.x, acc[rr][m]);
                        acc[rr][m] = fmaf(av[rr].y, wv.y, acc[rr][m]);
                        acc[rr][m] = fmaf(av[rr].z, wv.z, acc[rr][m]);
                        acc[rr][m] = fmaf(av[rr].w, wv.w, acc[rr][m]);
                    }
                }
            }
        }
        __syncthreads();
        #pragma unroll
        for (int m = 0; m < 4; m++) {
            int n = j + 128 * m;
            float bv = b_in[n];
            #pragma unroll
            for (int rr = 0; rr < 7; rr++)
                hA[(ig * 7 + rr) * Hdim + n] = __fadd_rn(acc[rr][m], bv);
        }
        __syncthreads();
    }

    float* hOld = hA;
    float* hNew = hB;

    for (int step = 0; step < Csteps; step++) {
        // ---- gate GEMMs: FFMA2, register pairing, double-buffered staging ----
        #pragma unroll 1
        for (int jc = 0; jc < 4; jc++) {
            unsigned long long accp[7][2];
            #pragma unroll
            for (int rr = 0; rr < 7; rr++) { accp[rr][0] = 0ULL; accp[rr][1] = 0ULL; }

            float* bufA = Wp;
            float* bufB = Wp + 10240;
            float4 pre[4];
            // prefetch + stage tile 0
            #pragma unroll
            for (int it = 0; it < 4; it++) {
                int id = t + it * NTHR;
                int c = id >> 2, s = id & 3;
                int n = (c >> 7) * Hdim + jc * 128 + (c & 127);
                pre[it] = *(const float4*)(w_hh + (long)n * Hdim + s * 4);
            }
            #pragma unroll
            for (int it = 0; it < 4; it++) {
                int id = t + it * NTHR;
                int c = id >> 2, s = id & 3;
                *(float4*)(bufA + c * WSTR + s * 4) = pre[it];
            }
            __syncthreads();

            for (int i = 0; i < Hdim / KT; i++) {
                const int k0 = i * KT;
                float* cur = (i & 1) ? bufB : bufA;
                float* nxt = (i & 1) ? bufA : bufB;
                if (i + 1 < Hdim / KT) {
                    #pragma unroll
                    for (int it = 0; it < 4; it++) {
                        int id = t + it * NTHR;
                        int c = id >> 2, s = id & 3;
                        int n = (c >> 7) * Hdim + jc * 128 + (c & 127);
                        pre[it] = *(const float4*)(w_hh + (long)n * Hdim + k0 + KT + s * 4);
                    }
                }
                #pragma unroll
                for (int kk = 0; kk < KT; kk += 4) {
                    // weight pairs (lo=gate 2P, hi=gate 2P+1), packed in regs
                    float4 w0a = *(const float4*)(cur + (0 * 128 + j) * WSTR + kk);
                    float4 w0b = *(const float4*)(cur + (1 * 128 + j) * WSTR + kk);
                    float4 w1a = *(const float4*)(cur + (2 * 128 + j) * WSTR + kk);
                    float4 w1b = *(const float4*)(cur + (3 * 128 + j) * WSTR + kk);
                    unsigned long long wp0[4], wp1[4];
                    wp0[0] = pack2(w0a.x, w0b.x); wp0[1] = pack2(w0a.y, w0b.y);
                    wp0[2] = pack2(w0a.z, w0b.z); wp0[3] = pack2(w0a.w, w0b.w);
                    wp1[0] = pack2(w1a.x, w1b.x); wp1[1] = pack2(w1a.y, w1b.y);
                    wp1[2] = pack2(w1a.z, w1b.z); wp1[3] = pack2(w1a.w, w1b.w);
                    #pragma unroll
                    for (int rr = 0; rr < 7; rr++) {
                        float4 a = *(const float4*)(hOld + (ig * 7 + rr) * Hdim + k0 + kk);
                        unsigned long long a0 = pack2(a.x, a.x);
                        unsigned long long a1 = pack2(a.y, a.y);
                        unsigned long long a2 = pack2(a.z, a.z);
                        unsigned long long a3 = pack2(a.w, a.w);
                        // ascending k in each chain
                        ffma2(accp[rr][0], a0, wp0[0]); ffma2(accp[rr][1], a0, wp1[0]);
                        ffma2(accp[rr][0], a1, wp0[1]); ffma2(accp[rr][1], a1, wp1[1]);
                        ffma2(accp[rr][0], a2, wp0[2]); ffma2(accp[rr][1], a2, wp1[2]);
                        ffma2(accp[rr][0], a3, wp0[3]); ffma2(accp[rr][1], a3, wp1[3]);
                    }
                }
                if (i + 1 < Hdim / KT) {
                    #pragma unroll
                    for (int it = 0; it < 4; it++) {
                        int id = t + it * NTHR;
                        int c = id >> 2, s = id & 3;
                        *(float4*)(nxt + c * WSTR + s * 4) = pre[it];
                    }
                }
                __syncthreads();
            }

            // epilogue
            #pragma unroll
            for (int rr = 0; rr < 7; rr++) {
                int r = ig * 7 + rr;
                int xidx = idxS[r];
                float g4[4];
                #pragma unroll
                for (int P = 0; P < 2; P++) {
                    unsigned int lo, hi;
                    asm("mov.b64 {%0,%1}, %2;" : "=r"(lo), "=r"(hi) : "l"(accp[rr][P]));
                    int n0 = (2 * P) * Hdim + jc * 128 + j;
                    int n1 = (2 * P + 1) * Hdim + jc * 128 + j;
                    g4[2 * P] = __fadd_rn(
                        __fadd_rn(g_wihT[xidx * (4 * Hdim) + n0], __uint_as_float(lo)),
                        biasS[n0]);
                    g4[2 * P + 1] = __fadd_rn(
                        __fadd_rn(g_wihT[xidx * (4 * Hdim) + n1], __uint_as_float(hi)),
                        biasS[n1]);
                }
                float ii = sigmoid_xla(g4[0]);
                float ff = sigmoid_xla(g4[1]);
                float gg = tanh_xla(g4[2]);
                float oo = sigmoid_xla(g4[3]);
                float cold = cloc[jc * 7 + rr];
                float cc = __fadd_rn(__fmul_rn(ff, cold), __fmul_rn(ii, gg));
                cloc[jc * 7 + rr] = cc;
                hNew[r * Hdim + jc * 128 + j] = __fmul_rn(oo, tanh_xla(cc));
            }
        }

        // ---- logits = hNew @ w_out.T + b_out (scalar, double-buffered) ----
        {
            float* bufA = Wp;
            float* bufB = Wp + 2560;
            float acc[7];
            #pragma unroll
            for (int rr = 0; rr < 7; rr++) acc[rr] = 0.0f;
            float4 pre;
            {
                int c = t >> 2, s = t & 3;
                pre = *(const float4*)(w_out + (long)c * Hdim + s * 4);
                *(float4*)(bufA + c * WSTR + s * 4) = pre;
            }
            __syncthreads();   // also orders hNew writes before reads
            for (int i = 0; i < Hdim / KT; i++) {
                const int k0 = i * KT;
                float* cur = (i & 1) ? bufB : bufA;
                float* nxt = (i & 1) ? bufA : bufB;
                int c = t >> 2, s = t & 3;
                if (i + 1 < Hdim / KT)
                    pre = *(const float4*)(w_out + (long)c * Hdim + k0 + KT + s * 4);
                #pragma unroll
                for (int kk = 0; kk < KT; kk += 4) {
                    float4 wv = *(const float4*)(cur + j * WSTR + kk);
                    #pragma unroll
                    for (int rr = 0; rr < 7; rr++) {
                        float4 av = *(const float4*)(hNew + (ig * 7 + rr) * Hdim + k0 + kk);
                        acc[rr] = fmaf(av.x, wv.x, acc[rr]);
                        acc[rr] = fmaf(av.y, wv.y, acc[rr]);
                        acc[rr] = fmaf(av.z, wv.z, acc[rr]);
                        acc[rr] = fmaf(av.w, wv.w, acc[rr]);
                    }
                }
                if (i + 1 < Hdim / KT)
                    *(float4*)(nxt + c * WSTR + s * 4) = pre;
                __syncthreads();
            }
            #pragma unroll
            for (int rr = 0; rr < 7; rr++) {
                int r = ig * 7 + rr;
                int rg = min(rowBase + r, NROWS - 1);
                float v = __fadd_rn(acc[rr], boutS[j]);
                logitsS[r * Adim + j] = v;
                out[((long)rg * Csteps + step) * Adim + j] = v;
            }
        }
        __syncthreads();

        // ---- argmax (first-max semantics) ----
        for (int r = warp; r < Rrows; r += 16) {
            float best = -INFINITY; int bi = 0;
            #pragma unroll
            for (int q = 0; q < 4; q++) {
                int a = lane + 32 * q;
                float v = logitsS[r * Adim + a];
                if (v > best) { best = v; bi = a; }
            }
            #pragma unroll
            for (int off = 16; off; off >>= 1) {
                float ov = __shfl_down_sync(0xffffffff, best, off);
                int   oi = __shfl_down_sync(0xffffffff, bi, off);
                if (ov > best || (ov == best && oi < bi)) { best = ov; bi = oi; }
            }
            if (lane == 0) idxS[r] = bi;
        }
        __syncthreads();

        float* tmp = hOld; hOld = hNew; hNew = tmp;
    }
}

extern "C" void kernel_launch(void* const* d_in, const int* in_sizes, int n_in,
                              void* d_out, int out_size) {
    const float* qr    = (const float*)d_in[0];
    const float* w_in  = (const float*)d_in[1];
    const float* b_in  = (const float*)d_in[2];
    const float* w_ih  = (const float*)d_in[3];
    const float* w_hh  = (const float*)d_in[4];
    const float* b_ih  = (const float*)d_in[5];
    const float* b_hh  = (const float*)d_in[6];
    const float* w_out = (const float*)d_in[7];
    const float* b_out = (const float*)d_in[8];
    float* out = (float*)d_out;

    transpose_wih_kernel<<<(Adim * 4 * Hdim + 255) / 256, 256>>>(w_ih);

    const int smemFloats = 2 * Rrows * Hdim + 2 * 10240 + 4 * Hdim + Adim + 32;
    const int smemBytes = smemFloats * 4;
    cudaFuncSetAttribute(chardecoder_kernel,
                         cudaFuncAttributeMaxDynamicSharedMemorySize, smemBytes);
    chardecoder_kernel<<<NCTAS, NTHR, smemBytes>>>(
        qr, w_in, b_in, w_hh, b_ih, b_hh, w_out, b_out, out);
}